// round 13
// baseline (speedup 1.0000x reference)
#include <cuda_runtime.h>
#include <cuda_bf16.h>
#include <math.h>
#include <stdint.h>

#define BB 64
#define LL 1024
#define DD 512
#define HH 1024
#define GG 4096
#define NCTA 128
#define NT 256

// ---- phase-2 dynamic smem map: B slab + 2 gate boards ----
#define SM_BHI 0                      // 32 x 1024 bf16 hi (swizzled)  64KB
#define SM_BLO 65536                  // lo                            64KB
#define SM_D   131072                 // 2 x (64 x 36) fp32 gate boards
#define SMEM2_TOTAL (SM_D + 2 * 64 * 36 * 4)   // 149504

// ---- phase-1 dynamic smem: 2 bufs x 64KB ----
#define SMEM1_TOTAL 131072

#define NX8 ((65536 * 512) / 8)
#define NW8 ((4096 * 512) / 8)

static __device__ float g_gx[(size_t)LL * BB * GG];   // [t][b][4H]
static __device__ __align__(16) __nv_bfloat16 g_xhi[(size_t)65536 * 512];
static __device__ __align__(16) __nv_bfloat16 g_xlo[(size_t)65536 * 512];
static __device__ __align__(16) __nv_bfloat16 g_whi[(size_t)4096 * 512];
static __device__ __align__(16) __nv_bfloat16 g_wlo[(size_t)4096 * 512];
// h published as pre-shuffled mma A-fragments:
// [buf][hi/lo][ktile 64][mtile 4][lane 32][reg 4] (uint32 = bf16x2)
static __device__ __align__(16) unsigned g_hfrag[2][2][64][4][32][4];
static __device__ unsigned g_bar[LL];
static __device__ int g_mask_mode;

__device__ __forceinline__ uint32_t smem_u32(const void* p) {
    uint32_t a;
    asm("{ .reg .u64 t; cvta.to.shared.u64 t, %1; cvt.u32.u64 %0, t; }" : "=r"(a) : "l"(p));
    return a;
}
__device__ __forceinline__ unsigned ldacq(const unsigned* p) {
    unsigned v;
    asm volatile("ld.acquire.gpu.global.u32 %0, [%1];" : "=r"(v) : "l"(p) : "memory");
    return v;
}
__device__ __forceinline__ void atomrel_add(unsigned* p, unsigned v) {
    unsigned old;
    asm volatile("atom.release.gpu.global.add.u32 %0, [%1], %2;"
                 : "=r"(old) : "l"(p), "r"(v) : "memory");
}
#define LDSM4(r, addr) asm volatile( \
    "ldmatrix.sync.aligned.m8n8.x4.shared.b16 {%0,%1,%2,%3}, [%4];" \
    : "=r"((r)[0]), "=r"((r)[1]), "=r"((r)[2]), "=r"((r)[3]) : "r"(addr))
#define LDSM2(r, addr) asm volatile( \
    "ldmatrix.sync.aligned.m8n8.x2.shared.b16 {%0,%1}, [%2];" \
    : "=r"((r)[0]), "=r"((r)[1]) : "r"(addr))
#define MMA16816(d, a, b) asm volatile( \
    "mma.sync.aligned.m16n8k16.row.col.f32.bf16.bf16.f32 " \
    "{%0,%1,%2,%3}, {%4,%5,%6,%7}, {%8,%9}, {%0,%1,%2,%3};" \
    : "+f"((d)[0]), "+f"((d)[1]), "+f"((d)[2]), "+f"((d)[3]) \
    : "r"((a)[0]), "r"((a)[1]), "r"((a)[2]), "r"((a)[3]), "r"((b)[0]), "r"((b)[1]))
#define CPA16(dst, src) asm volatile( \
    "cp.async.cg.shared.global [%0], [%1], 16;" :: "r"(dst), "l"(src))
#define CPCOMMIT() asm volatile("cp.async.commit_group;" ::: "memory")
#define CPWAIT0() asm volatile("cp.async.wait_group 0;" ::: "memory")

__device__ __forceinline__ float sigf(float x) { return 1.0f / (1.0f + __expf(-x)); }
__device__ __forceinline__ float tanhf_fast(float x) {
    float ax = fabsf(x);
    float e = __expf(2.0f * ax);
    float t = 1.0f - 2.0f / (e + 1.0f);
    return copysignf(t, x);
}

// ---------------- init --------------------------------------------------------
__global__ void init_kernel(const void* mask)
{
    int i = blockIdx.x * blockDim.x + threadIdx.x;
    // zero frag buffer 0 (h = 0): first 65536 words of g_hfrag
    ((unsigned*)g_hfrag)[i] = 0u;
    if (i < LL) g_bar[i] = 0u;
    if (i == 0) {
        int v = *(const int*)mask;          // lengths >= 512 -> mask[0,0..3] true
        if (v == 1)               g_mask_mode = 1;
        else if (v == 0x3F800000) g_mask_mode = 2;
        else                      g_mask_mode = 0;
    }
}

// ---------------- prep: fp32 -> bf16 hi/lo for X and Wih ---------------------
__global__ void convert_kernel(const float* __restrict__ X, const float* __restrict__ W)
{
    size_t s = (size_t)blockIdx.x * blockDim.x + threadIdx.x;
    const float* src;
    __nv_bfloat16 *dh, *dl;
    if (s < NX8)            { src = X + s * 8; dh = g_xhi + s * 8; dl = g_xlo + s * 8; }
    else if (s < NX8 + NW8) { size_t u = s - NX8; src = W + u * 8; dh = g_whi + u * 8; dl = g_wlo + u * 8; }
    else return;
    float4 f0 = *(const float4*)(src);
    float4 f1 = *(const float4*)(src + 4);
    float v[8] = {f0.x, f0.y, f0.z, f0.w, f1.x, f1.y, f1.z, f1.w};
    __align__(16) __nv_bfloat16 hi[8], lo[8];
#pragma unroll
    for (int j = 0; j < 8; j++) {
        __nv_bfloat16 h = __float2bfloat16(v[j]);
        hi[j] = h;
        lo[j] = __float2bfloat16(v[j] - __bfloat162float(h));
    }
    *(uint4*)dh = *(uint4*)hi;
    *(uint4*)dl = *(uint4*)lo;
}

// ---------------- phase 1: g_gx = X @ Wih^T + biases (bf16 hi/lo HMMA) -------
__global__ __launch_bounds__(256, 1)
void gemm_x_mma(const float* __restrict__ bih, const float* __restrict__ bhh)
{
    extern __shared__ __align__(16) char sm[];
    const uint32_t smb = smem_u32(sm);
    const int tid = threadIdx.x, lane = tid & 31, w = tid >> 5;
    const int wm = w & 1, wn = w >> 1;
    const int m0 = blockIdx.y * 128, n0 = blockIdx.x * 128;

    const int seg = lane >> 3, rr = lane & 7;
    const int adk = seg >> 1, bseg = seg & 1;

    const int lrow0 = tid >> 3, lc8 = tid & 7;
    const int soff0 = lrow0 * 128 + ((lc8 ^ (lrow0 & 7)) << 4);
    const __nv_bfloat16* xh = g_xhi + (size_t)(m0 + lrow0) * DD + lc8 * 8;
    const __nv_bfloat16* xl = g_xlo + (size_t)(m0 + lrow0) * DD + lc8 * 8;
    const __nv_bfloat16* wh = g_whi + (size_t)(n0 + lrow0) * DD + lc8 * 8;
    const __nv_bfloat16* wl = g_wlo + (size_t)(n0 + lrow0) * DD + lc8 * 8;

    int arow_off[4], brow_off[4];
#pragma unroll
    for (int mi = 0; mi < 4; mi++)
        arow_off[mi] = (wm * 64 + mi * 16 + ((seg & 1) << 3) + rr) * 128;
#pragma unroll
    for (int j = 0; j < 4; j++)
        brow_off[j] = (wn * 32 + j * 8 + rr) * 128;

    float bj0[4], bj1[4];
#pragma unroll
    for (int j = 0; j < 4; j++) {
        int col = n0 + wn * 32 + j * 8 + (lane & 3) * 2;
        bj0[j] = bih[col] + bhh[col];
        bj1[j] = bih[col + 1] + bhh[col + 1];
    }

    float acc[4][4][4];
#pragma unroll
    for (int mi = 0; mi < 4; mi++)
#pragma unroll
        for (int j = 0; j < 4; j++)
#pragma unroll
            for (int q = 0; q < 4; q++) acc[mi][j][q] = 0.0f;

    {
        uint32_t base = smb;
#pragma unroll
        for (int q = 0; q < 4; q++) {
            int go = q * 32 * DD;
            CPA16(base + soff0 + q * 4096,         xh + go);
            CPA16(base + 16384 + soff0 + q * 4096, xl + go);
            CPA16(base + 32768 + soff0 + q * 4096, wh + go);
            CPA16(base + 49152 + soff0 + q * 4096, wl + go);
        }
        CPCOMMIT();
    }

    for (int ck = 0; ck < 8; ++ck) {
        CPWAIT0();
        __syncthreads();
        if (ck < 7) {
            uint32_t base = smb + ((ck + 1) & 1) * 65536;
            int kofs = (ck + 1) * 64;
#pragma unroll
            for (int q = 0; q < 4; q++) {
                int go = q * 32 * DD + kofs;
                CPA16(base + soff0 + q * 4096,         xh + go);
                CPA16(base + 16384 + soff0 + q * 4096, xl + go);
                CPA16(base + 32768 + soff0 + q * 4096, wh + go);
                CPA16(base + 49152 + soff0 + q * 4096, wl + go);
            }
            CPCOMMIT();
        }
        const uint32_t bufA = smb + (ck & 1) * 65536;
        const uint32_t bufB = bufA + 32768;
#pragma unroll
        for (int ks = 0; ks < 4; ++ks) {
            uint32_t ah[4][4], al[4][4], bh[4][2], bl[4][2];
            const int ca = ((2 * ks + adk) ^ rr) << 4;
            const int cb = ((2 * ks + bseg) ^ rr) << 4;
#pragma unroll
            for (int mi = 0; mi < 4; mi++) {
                LDSM4(ah[mi], bufA + arow_off[mi] + ca);
                LDSM4(al[mi], bufA + 16384 + arow_off[mi] + ca);
            }
#pragma unroll
            for (int j = 0; j < 4; j++) {
                LDSM2(bh[j], bufB + brow_off[j] + cb);
                LDSM2(bl[j], bufB + 16384 + brow_off[j] + cb);
            }
#pragma unroll
            for (int mi = 0; mi < 4; mi++)
#pragma unroll
                for (int j = 0; j < 4; j++) {
                    MMA16816(acc[mi][j], ah[mi], bh[j]);
                    MMA16816(acc[mi][j], al[mi], bh[j]);
                    MMA16816(acc[mi][j], ah[mi], bl[j]);
                }
        }
        __syncthreads();
    }

#pragma unroll
    for (int mi = 0; mi < 4; mi++) {
        int r0 = m0 + wm * 64 + mi * 16 + (lane >> 2);
        int r1 = r0 + 8;
        float* d0 = g_gx + ((size_t)(r0 & 1023) * BB + (r0 >> 10)) * GG;
        float* d1 = g_gx + ((size_t)(r1 & 1023) * BB + (r1 >> 10)) * GG;
        int colb = n0 + wn * 32 + (lane & 3) * 2;
#pragma unroll
        for (int j = 0; j < 4; j++) {
            int col = colb + j * 8;
            *(float2*)(d0 + col) = make_float2(acc[mi][j][0] + bj0[j], acc[mi][j][1] + bj1[j]);
            *(float2*)(d1 + col) = make_float2(acc[mi][j][2] + bj0[j], acc[mi][j][3] + bj1[j]);
        }
    }
}

// ---------------- phase 2: persistent HMMA recurrence, k-split warps ---------
// warp w: k-half = w>>2, m-tile = w&3; each warp computes its m-tile x ALL 4
// n8-tiles for its k-half -> every A fragment loaded exactly once per CTA.
// Static loads (gx, mask, B kt0) pipelined across the barrier.
__global__ __launch_bounds__(NT, 1)
void lstm_mma_kernel(const float* __restrict__ Whh,
                     const unsigned char* __restrict__ m8,
                     const int* __restrict__ m32,
                     const float* __restrict__ mf,
                     const float* __restrict__ wci,
                     const float* __restrict__ wcf,
                     const float* __restrict__ wco,
                     float* __restrict__ out)
{
    extern __shared__ __align__(16) char sm[];
    const uint32_t smb = smem_u32(sm);

    const int tid  = threadIdx.x;
    const int lane = tid & 31;
    const int w    = tid >> 5;
    const int h0   = blockIdx.x * 8;

    // one-time: W slab -> smem bf16 hi/lo, 32 rows x 1024 k, swizzled (2048B rows)
    for (int s = tid; s < 4096; s += NT) {
        int n = s >> 7, c = s & 127;
        int gr = (n >> 3) * HH + h0 + (n & 7);
        const float* wp = Whh + (size_t)gr * HH + c * 8;
        __align__(16) __nv_bfloat16 hi8[8], lo8[8];
#pragma unroll
        for (int j = 0; j < 8; j++) {
            float wv = wp[j];
            __nv_bfloat16 hb = __float2bfloat16(wv);
            hi8[j] = hb;
            lo8[j] = __float2bfloat16(wv - __bfloat162float(hb));
        }
        int off = n * 2048 + ((c ^ (n & 7)) << 4);
        *(uint4*)(sm + SM_BHI + off) = *(uint4*)hi8;
        *(uint4*)(sm + SM_BLO + off) = *(uint4*)lo8;
    }
    __syncthreads();

    // per-warp mma geometry: kh = k-half, mt = m-tile; all 4 n8-tiles
    const int kh  = w >> 2;
    const int mt  = w & 3;
    const int m0  = mt << 4;
    const int seg = lane >> 3, rr = lane & 7;
    const int brow_a = (((seg >> 1) << 3) + rr) * 2048;
    const int brow_b = ((16 + ((seg >> 1) << 3)) + rr) * 2048;
    const int bk_sel = seg & 1;
    float* Ds  = (float*)(sm + SM_D + kh * (64 * 36 * 4));
    float* Ds0 = (float*)(sm + SM_D);
    float* Ds1 = (float*)(sm + SM_D + 64 * 36 * 4);

    // epilogue geometry (tid < 128): row = tid>>1, col-half = tid&1
    const int erow  = tid >> 1;
    const int ehalf = tid & 1;
    // publisher geometry
    const int pkt   = blockIdx.x >> 1;
    const int pregb = (blockIdx.x & 1) * 2;

    // recurrent state (4 h-cols per thread)
    float c_reg[4], h_reg[4], rci[4], rcf[4], rco[4];
#pragma unroll
    for (int j = 0; j < 4; j++) { c_reg[j] = 0.0f; h_reg[j] = 0.0f; }
    if (tid < 128) {
#pragma unroll
        for (int j = 0; j < 4; j++) {
            int col = h0 + ehalf * 4 + j;
            rci[j] = wci[col]; rcf[j] = wcf[col]; rco[j] = wco[col];
        }
    }
    const int mmode = g_mask_mode;

// load B fragments for ktile `ktv` into register buffer `buf`
#define LOADB(buf, ktv) do {                                                  \
    const int _kg = ((kh * 32 + (ktv)) * 2 + bk_sel) ^ rr;                    \
    const uint32_t _ba = smb + SM_BHI + brow_a + (_kg << 4);                  \
    const uint32_t _bb = smb + SM_BHI + brow_b + (_kg << 4);                  \
    LDSM4(bh0[buf], _ba);                                                     \
    LDSM4(bh1[buf], _bb);                                                     \
    LDSM4(bl0[buf], _ba + 65536);                                             \
    LDSM4(bl1[buf], _bb + 65536);                                             \
} while (0)

// prefetch gx + mask for step `tv` into gz regs (tid<128 only)
#define LOADGZ(tv) do {                                                       \
    const float* gx = g_gx + ((size_t)(tv) * BB + erow) * GG + h0 + ehalf * 4;\
    *(float4*)(&gzi[0]) = *(const float4*)(gx);                               \
    *(float4*)(&gzf[0]) = *(const float4*)(gx + 1024);                        \
    *(float4*)(&gzg[0]) = *(const float4*)(gx + 2048);                        \
    *(float4*)(&gzo[0]) = *(const float4*)(gx + 3072);                        \
    if (mmode == 1)      mm = (m32[erow * LL + (tv)] != 0);                   \
    else if (mmode == 2) mm = (mf[erow * LL + (tv)] != 0.0f);                 \
    else                 mm = (m8[erow * LL + (tv)] != 0);                    \
} while (0)

    // persistent loop-carried prefetch state
    float gzi[4], gzf[4], gzg[4], gzo[4];
    bool mm = false;
    uint32_t bh0[2][4], bh1[2][4], bl0[2][4], bl1[2][4];

    if (tid < 128) LOADGZ(0);
    LOADB(0, 0);

    for (int t = 0; t < LL; ++t) {
        const int rbuf = t & 1;
        const unsigned* fph = &g_hfrag[rbuf][0][kh * 32][mt][lane][0];
        const unsigned* fpl = &g_hfrag[rbuf][1][kh * 32][mt][lane][0];

        float d[4][4];
#pragma unroll
        for (int j = 0; j < 4; j++)
#pragma unroll
            for (int q = 0; q < 4; q++) d[j][q] = 0.0f;

        // A-fragment stream: 8-deep register prefetch; B double-buffered regs
        uint4 ph[8], pl[8];
#pragma unroll
        for (int s = 0; s < 8; s++) {
            ph[s] = __ldcg((const uint4*)(fph + (size_t)s * 512));
            pl[s] = __ldcg((const uint4*)(fpl + (size_t)s * 512));
        }
#pragma unroll 8
        for (int kt = 0; kt < 32; ++kt) {
            const int cur = kt & 1, nxt = cur ^ 1;
            if (kt + 1 < 32) LOADB(nxt, kt + 1);
            uint32_t ah[4] = {ph[kt & 7].x, ph[kt & 7].y, ph[kt & 7].z, ph[kt & 7].w};
            uint32_t al[4] = {pl[kt & 7].x, pl[kt & 7].y, pl[kt & 7].z, pl[kt & 7].w};
            if (kt + 8 < 32) {
                ph[kt & 7] = __ldcg((const uint4*)(fph + (size_t)(kt + 8) * 512));
                pl[kt & 7] = __ldcg((const uint4*)(fpl + (size_t)(kt + 8) * 512));
            }
            MMA16816(d[0], ah, (bh0[cur] + 0)); MMA16816(d[1], ah, (bh0[cur] + 2));
            MMA16816(d[2], ah, (bh1[cur] + 0)); MMA16816(d[3], ah, (bh1[cur] + 2));
            MMA16816(d[0], al, (bh0[cur] + 0)); MMA16816(d[1], al, (bh0[cur] + 2));
            MMA16816(d[2], al, (bh1[cur] + 0)); MMA16816(d[3], al, (bh1[cur] + 2));
            MMA16816(d[0], ah, (bl0[cur] + 0)); MMA16816(d[1], ah, (bl0[cur] + 2));
            MMA16816(d[2], ah, (bl1[cur] + 0)); MMA16816(d[3], ah, (bl1[cur] + 2));
        }

        // accumulators -> this k-half's gate board
        {
            const int gid = lane >> 2, tig = lane & 3;
            const int dr0 = m0 + gid, dr1 = m0 + gid + 8;
#pragma unroll
            for (int j = 0; j < 4; j++) {
                int cc = j * 8 + 2 * tig;
                *(float2*)(&Ds[dr0 * 36 + cc]) = make_float2(d[j][0], d[j][1]);
                *(float2*)(&Ds[dr1 * 36 + cc]) = make_float2(d[j][2], d[j][3]);
            }
        }
        __syncthreads();

        // epilogue: 128 threads; thread owns 4 h-cols (all 4 gates) of one row
        if (tid < 128) {
            const int row = erow;
            const int cb  = ehalf * 4;
            float hv[4];
#pragma unroll
            for (int j = 0; j < 4; j++) {
                int cc = cb + j;
                float vi = gzi[j] + Ds0[row * 36 + cc]      + Ds1[row * 36 + cc];
                float vf = gzf[j] + Ds0[row * 36 + 8 + cc]  + Ds1[row * 36 + 8 + cc];
                float vg = gzg[j] + Ds0[row * 36 + 16 + cc] + Ds1[row * 36 + 16 + cc];
                float vo = gzo[j] + Ds0[row * 36 + 24 + cc] + Ds1[row * 36 + 24 + cc];
                float cold = c_reg[j];
                float iv = sigf(vi + rci[j] * cold);
                float fv = sigf(vf + rcf[j] * cold);
                float gv = tanhf_fast(vg);
                float cy = fv * cold + iv * gv;
                float ov = sigf(vo + rco[j] * cy);
                float hy = ov * tanhf_fast(cy);
                if (mm) { c_reg[j] = cy; h_reg[j] = hy; }
                hv[j] = h_reg[j];
            }
            float* op = out + ((size_t)row * LL + t) * HH + h0 + cb;
            __stcg((float4*)op, make_float4(hv[0], hv[1], hv[2], hv[3]));

            // publish h as pre-shuffled mma A-fragments (hi/lo): 2 pairs
            const int wbuf  = (t + 1) & 1;
            const int pmt   = row >> 4;
            const int lbase = 4 * (row & 7);
            const int preg  = pregb + ((row & 15) >> 3);
            unsigned* dsth = &g_hfrag[wbuf][0][pkt][pmt][0][0];
            unsigned* dstl = &g_hfrag[wbuf][1][pkt][pmt][0][0];
#pragma unroll
            for (int p2 = 0; p2 < 2; p2++) {
                const int p = ehalf * 2 + p2;
                float v0 = hv[2 * p2], v1 = hv[2 * p2 + 1];
                __nv_bfloat16 h0b = __float2bfloat16(v0);
                __nv_bfloat16 h1b = __float2bfloat16(v1);
                __nv_bfloat16 l0b = __float2bfloat16(v0 - __bfloat162float(h0b));
                __nv_bfloat16 l1b = __float2bfloat16(v1 - __bfloat162float(h1b));
                unsigned uh = (unsigned)__bfloat16_as_ushort(h0b) |
                              ((unsigned)__bfloat16_as_ushort(h1b) << 16);
                unsigned ul = (unsigned)__bfloat16_as_ushort(l0b) |
                              ((unsigned)__bfloat16_as_ushort(l1b) << 16);
                __stcg(&dsth[(lbase + p) * 4 + preg], uh);
                __stcg(&dstl[(lbase + p) * 4 + preg], ul);
            }

            if (t == LL - 1) {
                float* hf = out + (size_t)BB * LL * HH + row * HH + h0 + cb;
                float* cf = hf + (size_t)BB * HH;
                __stcg((float4*)hf, make_float4(hv[0], hv[1], hv[2], hv[3]));
                __stcg((float4*)cf, make_float4(c_reg[0], c_reg[1], c_reg[2], c_reg[3]));
            }
            // prefetch next step's static inputs off the critical path
            if (t + 1 < LL) LOADGZ(t + 1);
        }
        // restore B buf0 (kt=0 data; B static across steps) off the critical path
        LOADB(0, 0);

        // grid-wide barrier: bar.sync gives HB from all epilogue stores to tid 0;
        // release-atomic publishes them GPU-wide; waiters acquire-poll.
        __syncthreads();
        if (tid == 0) {
            atomrel_add(&g_bar[t], 1u);
            while (ldacq(&g_bar[t]) < (unsigned)gridDim.x) __nanosleep(64);
        }
        __syncthreads();
    }
#undef LOADB
#undef LOADGZ
}

// ---------------- launch ------------------------------------------------------
extern "C" void kernel_launch(void* const* d_in, const int* in_sizes, int n_in,
                              void* d_out, int out_size)
{
    (void)in_sizes; (void)n_in; (void)out_size;
    const float* X    = (const float*)d_in[0];
    const void*  mask = d_in[1];
    const float* Wih  = (const float*)d_in[2];
    const float* Whh  = (const float*)d_in[3];
    const float* bih  = (const float*)d_in[4];
    const float* bhh  = (const float*)d_in[5];
    const float* wci  = (const float*)d_in[6];
    const float* wcf  = (const float*)d_in[7];
    const float* wco  = (const float*)d_in[8];
    float* out = (float*)d_out;

    init_kernel<<<256, 256>>>(mask);
    convert_kernel<<<(NX8 + NW8 + 255) / 256, 256>>>(X, Wih);

    cudaFuncSetAttribute(gemm_x_mma,
                         cudaFuncAttributeMaxDynamicSharedMemorySize, SMEM1_TOTAL);
    dim3 g1(GG / 128, (BB * LL) / 128);
    gemm_x_mma<<<g1, 256, SMEM1_TOTAL>>>(bih, bhh);

    cudaFuncSetAttribute(lstm_mma_kernel,
                         cudaFuncAttributeMaxDynamicSharedMemorySize, SMEM2_TOTAL);
    lstm_mma_kernel<<<NCTA, NT, SMEM2_TOTAL>>>(Whh,
                                               (const unsigned char*)mask,
                                               (const int*)mask,
                                               (const float*)mask,
                                               wci, wcf, wco, out);
}

// round 14
// speedup vs baseline: 1.2082x; 1.2082x over previous
#include <cuda_runtime.h>
#include <cuda_bf16.h>
#include <cuda_fp16.h>
#include <math.h>
#include <stdint.h>

#define BB 64
#define LL 1024
#define DD 512
#define HH 1024
#define GG 4096
#define NCTA 128
#define NT 256

// ---- phase-2 dynamic smem map: B slab (fp16 hi + 2048x lo) + 2 gate boards ----
#define SM_BHI 0                      // 32 x 1024 fp16 hi (swizzled)  64KB
#define SM_BLO 65536                  // 2048-scaled lo                64KB
#define SM_D   131072                 // 2 x (64 x 36) fp32 gate boards
#define SMEM2_TOTAL (SM_D + 2 * 64 * 36 * 4)   // 149504

// ---- phase-1 dynamic smem: 2 bufs x 64KB ----
#define SMEM1_TOTAL 131072

#define NX8 ((65536 * 512) / 8)
#define NW8 ((4096 * 512) / 8)

#define INV2048 4.8828125e-4f

static __device__ float g_gx[(size_t)LL * BB * GG];   // [t][b][4H]
static __device__ __align__(16) __nv_bfloat16 g_xhi[(size_t)65536 * 512];
static __device__ __align__(16) __nv_bfloat16 g_xlo[(size_t)65536 * 512];
static __device__ __align__(16) __nv_bfloat16 g_whi[(size_t)4096 * 512];
static __device__ __align__(16) __nv_bfloat16 g_wlo[(size_t)4096 * 512];
// h published as pre-shuffled fp16 mma A-fragments:
// [buf][ktile 64][mtile 4][lane 32][reg 4] (uint32 = fp16x2)
static __device__ __align__(16) unsigned g_hfrag[2][64][4][32][4];
static __device__ unsigned g_bar[LL];
static __device__ int g_mask_mode;

__device__ __forceinline__ uint32_t smem_u32(const void* p) {
    uint32_t a;
    asm("{ .reg .u64 t; cvta.to.shared.u64 t, %1; cvt.u32.u64 %0, t; }" : "=r"(a) : "l"(p));
    return a;
}
__device__ __forceinline__ unsigned ldacq(const unsigned* p) {
    unsigned v;
    asm volatile("ld.acquire.gpu.global.u32 %0, [%1];" : "=r"(v) : "l"(p) : "memory");
    return v;
}
__device__ __forceinline__ void atomrel_add(unsigned* p, unsigned v) {
    unsigned old;
    asm volatile("atom.release.gpu.global.add.u32 %0, [%1], %2;"
                 : "=r"(old) : "l"(p), "r"(v) : "memory");
}
#define LDSM4(r, addr) asm volatile( \
    "ldmatrix.sync.aligned.m8n8.x4.shared.b16 {%0,%1,%2,%3}, [%4];" \
    : "=r"((r)[0]), "=r"((r)[1]), "=r"((r)[2]), "=r"((r)[3]) : "r"(addr))
#define LDSM2(r, addr) asm volatile( \
    "ldmatrix.sync.aligned.m8n8.x2.shared.b16 {%0,%1}, [%2];" \
    : "=r"((r)[0]), "=r"((r)[1]) : "r"(addr))
// bf16 mma (phase 1)
#define MMA16816(d, a, b) asm volatile( \
    "mma.sync.aligned.m16n8k16.row.col.f32.bf16.bf16.f32 " \
    "{%0,%1,%2,%3}, {%4,%5,%6,%7}, {%8,%9}, {%0,%1,%2,%3};" \
    : "+f"((d)[0]), "+f"((d)[1]), "+f"((d)[2]), "+f"((d)[3]) \
    : "r"((a)[0]), "r"((a)[1]), "r"((a)[2]), "r"((a)[3]), "r"((b)[0]), "r"((b)[1]))
// fp16 mma (phase 2)
#define MMAH16816(d, a, b) asm volatile( \
    "mma.sync.aligned.m16n8k16.row.col.f32.f16.f16.f32 " \
    "{%0,%1,%2,%3}, {%4,%5,%6,%7}, {%8,%9}, {%0,%1,%2,%3};" \
    : "+f"((d)[0]), "+f"((d)[1]), "+f"((d)[2]), "+f"((d)[3]) \
    : "r"((a)[0]), "r"((a)[1]), "r"((a)[2]), "r"((a)[3]), "r"((b)[0]), "r"((b)[1]))
#define CPA16(dst, src) asm volatile( \
    "cp.async.cg.shared.global [%0], [%1], 16;" :: "r"(dst), "l"(src))
#define CPCOMMIT() asm volatile("cp.async.commit_group;" ::: "memory")
#define CPWAIT0() asm volatile("cp.async.wait_group 0;" ::: "memory")

__device__ __forceinline__ float sigf(float x) { return 1.0f / (1.0f + __expf(-x)); }
__device__ __forceinline__ float tanhf_fast(float x) {
    float ax = fabsf(x);
    float e = __expf(2.0f * ax);
    float t = 1.0f - 2.0f / (e + 1.0f);
    return copysignf(t, x);
}

// ---------------- init --------------------------------------------------------
__global__ void init_kernel(const void* mask)
{
    int i = blockIdx.x * blockDim.x + threadIdx.x;
    // zero frag buffer 0 (h = 0): 64*4*32*4 = 32768 words
    if (i < 32768) ((unsigned*)g_hfrag)[i] = 0u;
    if (i < LL) g_bar[i] = 0u;
    if (i == 0) {
        int v = *(const int*)mask;          // lengths >= 512 -> mask[0,0..3] true
        if (v == 1)               g_mask_mode = 1;
        else if (v == 0x3F800000) g_mask_mode = 2;
        else                      g_mask_mode = 0;
    }
}

// ---------------- prep: fp32 -> bf16 hi/lo for X and Wih ---------------------
__global__ void convert_kernel(const float* __restrict__ X, const float* __restrict__ W)
{
    size_t s = (size_t)blockIdx.x * blockDim.x + threadIdx.x;
    const float* src;
    __nv_bfloat16 *dh, *dl;
    if (s < NX8)            { src = X + s * 8; dh = g_xhi + s * 8; dl = g_xlo + s * 8; }
    else if (s < NX8 + NW8) { size_t u = s - NX8; src = W + u * 8; dh = g_whi + u * 8; dl = g_wlo + u * 8; }
    else return;
    float4 f0 = *(const float4*)(src);
    float4 f1 = *(const float4*)(src + 4);
    float v[8] = {f0.x, f0.y, f0.z, f0.w, f1.x, f1.y, f1.z, f1.w};
    __align__(16) __nv_bfloat16 hi[8], lo[8];
#pragma unroll
    for (int j = 0; j < 8; j++) {
        __nv_bfloat16 h = __float2bfloat16(v[j]);
        hi[j] = h;
        lo[j] = __float2bfloat16(v[j] - __bfloat162float(h));
    }
    *(uint4*)dh = *(uint4*)hi;
    *(uint4*)dl = *(uint4*)lo;
}

// ---------------- phase 1: g_gx = X @ Wih^T + biases (bf16 hi/lo HMMA) -------
__global__ __launch_bounds__(256, 1)
void gemm_x_mma(const float* __restrict__ bih, const float* __restrict__ bhh)
{
    extern __shared__ __align__(16) char sm[];
    const uint32_t smb = smem_u32(sm);
    const int tid = threadIdx.x, lane = tid & 31, w = tid >> 5;
    const int wm = w & 1, wn = w >> 1;
    const int m0 = blockIdx.y * 128, n0 = blockIdx.x * 128;

    const int seg = lane >> 3, rr = lane & 7;
    const int adk = seg >> 1, bseg = seg & 1;

    const int lrow0 = tid >> 3, lc8 = tid & 7;
    const int soff0 = lrow0 * 128 + ((lc8 ^ (lrow0 & 7)) << 4);
    const __nv_bfloat16* xh = g_xhi + (size_t)(m0 + lrow0) * DD + lc8 * 8;
    const __nv_bfloat16* xl = g_xlo + (size_t)(m0 + lrow0) * DD + lc8 * 8;
    const __nv_bfloat16* wh = g_whi + (size_t)(n0 + lrow0) * DD + lc8 * 8;
    const __nv_bfloat16* wl = g_wlo + (size_t)(n0 + lrow0) * DD + lc8 * 8;

    int arow_off[4], brow_off[4];
#pragma unroll
    for (int mi = 0; mi < 4; mi++)
        arow_off[mi] = (wm * 64 + mi * 16 + ((seg & 1) << 3) + rr) * 128;
#pragma unroll
    for (int j = 0; j < 4; j++)
        brow_off[j] = (wn * 32 + j * 8 + rr) * 128;

    float bj0[4], bj1[4];
#pragma unroll
    for (int j = 0; j < 4; j++) {
        int col = n0 + wn * 32 + j * 8 + (lane & 3) * 2;
        bj0[j] = bih[col] + bhh[col];
        bj1[j] = bih[col + 1] + bhh[col + 1];
    }

    float acc[4][4][4];
#pragma unroll
    for (int mi = 0; mi < 4; mi++)
#pragma unroll
        for (int j = 0; j < 4; j++)
#pragma unroll
            for (int q = 0; q < 4; q++) acc[mi][j][q] = 0.0f;

    {
        uint32_t base = smb;
#pragma unroll
        for (int q = 0; q < 4; q++) {
            int go = q * 32 * DD;
            CPA16(base + soff0 + q * 4096,         xh + go);
            CPA16(base + 16384 + soff0 + q * 4096, xl + go);
            CPA16(base + 32768 + soff0 + q * 4096, wh + go);
            CPA16(base + 49152 + soff0 + q * 4096, wl + go);
        }
        CPCOMMIT();
    }

    for (int ck = 0; ck < 8; ++ck) {
        CPWAIT0();
        __syncthreads();
        if (ck < 7) {
            uint32_t base = smb + ((ck + 1) & 1) * 65536;
            int kofs = (ck + 1) * 64;
#pragma unroll
            for (int q = 0; q < 4; q++) {
                int go = q * 32 * DD + kofs;
                CPA16(base + soff0 + q * 4096,         xh + go);
                CPA16(base + 16384 + soff0 + q * 4096, xl + go);
                CPA16(base + 32768 + soff0 + q * 4096, wh + go);
                CPA16(base + 49152 + soff0 + q * 4096, wl + go);
            }
            CPCOMMIT();
        }
        const uint32_t bufA = smb + (ck & 1) * 65536;
        const uint32_t bufB = bufA + 32768;
#pragma unroll
        for (int ks = 0; ks < 4; ++ks) {
            uint32_t ah[4][4], al[4][4], bh[4][2], bl[4][2];
            const int ca = ((2 * ks + adk) ^ rr) << 4;
            const int cb = ((2 * ks + bseg) ^ rr) << 4;
#pragma unroll
            for (int mi = 0; mi < 4; mi++) {
                LDSM4(ah[mi], bufA + arow_off[mi] + ca);
                LDSM4(al[mi], bufA + 16384 + arow_off[mi] + ca);
            }
#pragma unroll
            for (int j = 0; j < 4; j++) {
                LDSM2(bh[j], bufB + brow_off[j] + cb);
                LDSM2(bl[j], bufB + 16384 + brow_off[j] + cb);
            }
#pragma unroll
            for (int mi = 0; mi < 4; mi++)
#pragma unroll
                for (int j = 0; j < 4; j++) {
                    MMA16816(acc[mi][j], ah[mi], bh[j]);
                    MMA16816(acc[mi][j], al[mi], bh[j]);
                    MMA16816(acc[mi][j], ah[mi], bl[j]);
                }
        }
        __syncthreads();
    }

#pragma unroll
    for (int mi = 0; mi < 4; mi++) {
        int r0 = m0 + wm * 64 + mi * 16 + (lane >> 2);
        int r1 = r0 + 8;
        float* d0 = g_gx + ((size_t)(r0 & 1023) * BB + (r0 >> 10)) * GG;
        float* d1 = g_gx + ((size_t)(r1 & 1023) * BB + (r1 >> 10)) * GG;
        int colb = n0 + wn * 32 + (lane & 3) * 2;
#pragma unroll
        for (int j = 0; j < 4; j++) {
            int col = colb + j * 8;
            *(float2*)(d0 + col) = make_float2(acc[mi][j][0] + bj0[j], acc[mi][j][1] + bj1[j]);
            *(float2*)(d1 + col) = make_float2(acc[mi][j][2] + bj0[j], acc[mi][j][3] + bj1[j]);
        }
    }
}

// ---------------- phase 2: persistent fp16 HMMA recurrence, k-split warps ----
// h published as single fp16 A-frags; W = fp16 hi + 2048x fp16 lo (pass 2 into
// separate accumulator d2, scaled by 1/2048 at board store).
__global__ __launch_bounds__(NT, 1)
void lstm_mma_kernel(const float* __restrict__ Whh,
                     const unsigned char* __restrict__ m8,
                     const int* __restrict__ m32,
                     const float* __restrict__ mf,
                     const float* __restrict__ wci,
                     const float* __restrict__ wcf,
                     const float* __restrict__ wco,
                     float* __restrict__ out)
{
    extern __shared__ __align__(16) char sm[];
    const uint32_t smb = smem_u32(sm);

    const int tid  = threadIdx.x;
    const int lane = tid & 31;
    const int w    = tid >> 5;
    const int h0   = blockIdx.x * 8;

    // one-time: W slab -> smem fp16 hi + 2048x lo, 32 rows x 1024 k, swizzled
    for (int s = tid; s < 4096; s += NT) {
        int n = s >> 7, c = s & 127;
        int gr = (n >> 3) * HH + h0 + (n & 7);
        const float* wp = Whh + (size_t)gr * HH + c * 8;
        __align__(16) __half hi8[8], lo8[8];
#pragma unroll
        for (int j = 0; j < 8; j++) {
            float wv = wp[j];
            __half hb = __float2half_rn(wv);
            hi8[j] = hb;
            lo8[j] = __float2half_rn((wv - __half2float(hb)) * 2048.0f);
        }
        int off = n * 2048 + ((c ^ (n & 7)) << 4);
        *(uint4*)(sm + SM_BHI + off) = *(uint4*)hi8;
        *(uint4*)(sm + SM_BLO + off) = *(uint4*)lo8;
    }
    __syncthreads();

    // per-warp mma geometry: kh = k-half, mt = m-tile; all 4 n8-tiles
    const int kh  = w >> 2;
    const int mt  = w & 3;
    const int m0  = mt << 4;
    const int seg = lane >> 3, rr = lane & 7;
    const int brow_a = (((seg >> 1) << 3) + rr) * 2048;
    const int brow_b = ((16 + ((seg >> 1) << 3)) + rr) * 2048;
    const int bk_sel = seg & 1;
    float* Ds  = (float*)(sm + SM_D + kh * (64 * 36 * 4));
    float* Ds0 = (float*)(sm + SM_D);
    float* Ds1 = (float*)(sm + SM_D + 64 * 36 * 4);

    // epilogue geometry (tid < 128): row = tid>>1, col-half = tid&1
    const int erow  = tid >> 1;
    const int ehalf = tid & 1;
    // publisher geometry
    const int pkt   = blockIdx.x >> 1;
    const int pregb = (blockIdx.x & 1) * 2;

    // recurrent state (4 h-cols per thread)
    float c_reg[4], h_reg[4], rci[4], rcf[4], rco[4];
#pragma unroll
    for (int j = 0; j < 4; j++) { c_reg[j] = 0.0f; h_reg[j] = 0.0f; }
    if (tid < 128) {
#pragma unroll
        for (int j = 0; j < 4; j++) {
            int col = h0 + ehalf * 4 + j;
            rci[j] = wci[col]; rcf[j] = wcf[col]; rco[j] = wco[col];
        }
    }
    const int mmode = g_mask_mode;

// load B fragments for ktile `ktv` into register buffer `buf`
#define LOADB(buf, ktv) do {                                                  \
    const int _kg = ((kh * 32 + (ktv)) * 2 + bk_sel) ^ rr;                    \
    const uint32_t _ba = smb + SM_BHI + brow_a + (_kg << 4);                  \
    const uint32_t _bb = smb + SM_BHI + brow_b + (_kg << 4);                  \
    LDSM4(bh0[buf], _ba);                                                     \
    LDSM4(bh1[buf], _bb);                                                     \
    LDSM4(bl0[buf], _ba + 65536);                                             \
    LDSM4(bl1[buf], _bb + 65536);                                             \
} while (0)

    for (int t = 0; t < LL; ++t) {
        const int rbuf = t & 1;
        const unsigned* fph = &g_hfrag[rbuf][kh * 32][mt][lane][0];

        // prefetch x-projection + mask for the epilogue (128 threads)
        float gzi[4], gzf[4], gzg[4], gzo[4];
        bool mm = false;
        if (tid < 128) {
            const float* gx = g_gx + ((size_t)t * BB + erow) * GG + h0 + ehalf * 4;
            *(float4*)(&gzi[0]) = *(const float4*)(gx);
            *(float4*)(&gzf[0]) = *(const float4*)(gx + 1024);
            *(float4*)(&gzg[0]) = *(const float4*)(gx + 2048);
            *(float4*)(&gzo[0]) = *(const float4*)(gx + 3072);
            if (mmode == 1)      mm = (m32[erow * LL + t] != 0);
            else if (mmode == 2) mm = (mf[erow * LL + t] != 0.0f);
            else                 mm = (m8[erow * LL + t] != 0);
        }

        float d[4][4], d2[4][4];
#pragma unroll
        for (int j = 0; j < 4; j++)
#pragma unroll
            for (int q = 0; q < 4; q++) { d[j][q] = 0.0f; d2[j][q] = 0.0f; }

        // A-fragment stream: 8-deep register prefetch; B double-buffered regs
        uint4 ph[8];
#pragma unroll
        for (int s = 0; s < 8; s++)
            ph[s] = __ldcg((const uint4*)(fph + (size_t)s * 512));
        uint32_t bh0[2][4], bh1[2][4], bl0[2][4], bl1[2][4];
        LOADB(0, 0);
#pragma unroll 8
        for (int kt = 0; kt < 32; ++kt) {
            const int cur = kt & 1, nxt = cur ^ 1;
            if (kt + 1 < 32) LOADB(nxt, kt + 1);
            uint32_t ah[4] = {ph[kt & 7].x, ph[kt & 7].y, ph[kt & 7].z, ph[kt & 7].w};
            if (kt + 8 < 32)
                ph[kt & 7] = __ldcg((const uint4*)(fph + (size_t)(kt + 8) * 512));
            MMAH16816(d[0],  ah, (bh0[cur] + 0)); MMAH16816(d[1],  ah, (bh0[cur] + 2));
            MMAH16816(d[2],  ah, (bh1[cur] + 0)); MMAH16816(d[3],  ah, (bh1[cur] + 2));
            MMAH16816(d2[0], ah, (bl0[cur] + 0)); MMAH16816(d2[1], ah, (bl0[cur] + 2));
            MMAH16816(d2[2], ah, (bl1[cur] + 0)); MMAH16816(d2[3], ah, (bl1[cur] + 2));
        }

        // accumulators -> this k-half's gate board (fold 2048x lo pass)
        {
            const int gid = lane >> 2, tig = lane & 3;
            const int dr0 = m0 + gid, dr1 = m0 + gid + 8;
#pragma unroll
            for (int j = 0; j < 4; j++) {
                int cc = j * 8 + 2 * tig;
                *(float2*)(&Ds[dr0 * 36 + cc]) =
                    make_float2(d[j][0] + d2[j][0] * INV2048, d[j][1] + d2[j][1] * INV2048);
                *(float2*)(&Ds[dr1 * 36 + cc]) =
                    make_float2(d[j][2] + d2[j][2] * INV2048, d[j][3] + d2[j][3] * INV2048);
            }
        }
        __syncthreads();

        // epilogue: 128 threads; thread owns 4 h-cols (all 4 gates) of one row
        if (tid < 128) {
            const int row = erow;
            const int cb  = ehalf * 4;
            float hv[4];
#pragma unroll
            for (int j = 0; j < 4; j++) {
                int cc = cb + j;
                float vi = gzi[j] + Ds0[row * 36 + cc]      + Ds1[row * 36 + cc];
                float vf = gzf[j] + Ds0[row * 36 + 8 + cc]  + Ds1[row * 36 + 8 + cc];
                float vg = gzg[j] + Ds0[row * 36 + 16 + cc] + Ds1[row * 36 + 16 + cc];
                float vo = gzo[j] + Ds0[row * 36 + 24 + cc] + Ds1[row * 36 + 24 + cc];
                float cold = c_reg[j];
                float iv = sigf(vi + rci[j] * cold);
                float fv = sigf(vf + rcf[j] * cold);
                float gv = tanhf_fast(vg);
                float cy = fv * cold + iv * gv;
                float ov = sigf(vo + rco[j] * cy);
                float hy = ov * tanhf_fast(cy);
                if (mm) { c_reg[j] = cy; h_reg[j] = hy; }
                hv[j] = h_reg[j];
            }
            float* op = out + ((size_t)row * LL + t) * HH + h0 + cb;
            *(float4*)(op) = make_float4(hv[0], hv[1], hv[2], hv[3]);

            // publish h as pre-shuffled fp16 mma A-fragments: 2 packed pairs
            const int wbuf  = (t + 1) & 1;
            const int pmt   = row >> 4;
            const int lbase = 4 * (row & 7);
            const int preg  = pregb + ((row & 15) >> 3);
            unsigned* dsth = &g_hfrag[wbuf][pkt][pmt][0][0];
#pragma unroll
            for (int p2 = 0; p2 < 2; p2++) {
                const int p = ehalf * 2 + p2;
                __half h0h = __float2half_rn(hv[2 * p2]);
                __half h1h = __float2half_rn(hv[2 * p2 + 1]);
                unsigned uh = (unsigned)__half_as_ushort(h0h) |
                              ((unsigned)__half_as_ushort(h1h) << 16);
                dsth[(lbase + p) * 4 + preg] = uh;
            }

            if (t == LL - 1) {
                float* hf = out + (size_t)BB * LL * HH + row * HH + h0 + cb;
                float* cf = hf + (size_t)BB * HH;
                *(float4*)(hf) = make_float4(hv[0], hv[1], hv[2], hv[3]);
                *(float4*)(cf) = make_float4(c_reg[0], c_reg[1], c_reg[2], c_reg[3]);
            }
        }

        // grid-wide barrier: bar.sync gives HB from all epilogue stores to tid 0;
        // release-atomic publishes them GPU-wide; waiters acquire-poll.
        __syncthreads();
        if (tid == 0) {
            atomrel_add(&g_bar[t], 1u);
            while (ldacq(&g_bar[t]) < (unsigned)gridDim.x) __nanosleep(64);
        }
        __syncthreads();
    }
#undef LOADB
}

// ---------------- launch ------------------------------------------------------
extern "C" void kernel_launch(void* const* d_in, const int* in_sizes, int n_in,
                              void* d_out, int out_size)
{
    (void)in_sizes; (void)n_in; (void)out_size;
    const float* X    = (const float*)d_in[0];
    const void*  mask = d_in[1];
    const float* Wih  = (const float*)d_in[2];
    const float* Whh  = (const float*)d_in[3];
    const float* bih  = (const float*)d_in[4];
    const float* bhh  = (const float*)d_in[5];
    const float* wci  = (const float*)d_in[6];
    const float* wcf  = (const float*)d_in[7];
    const float* wco  = (const float*)d_in[8];
    float* out = (float*)d_out;

    init_kernel<<<256, 256>>>(mask);
    convert_kernel<<<(NX8 + NW8 + 255) / 256, 256>>>(X, Wih);

    cudaFuncSetAttribute(gemm_x_mma,
                         cudaFuncAttributeMaxDynamicSharedMemorySize, SMEM1_TOTAL);
    dim3 g1(GG / 128, (BB * LL) / 128);
    gemm_x_mma<<<g1, 256, SMEM1_TOTAL>>>(bih, bhh);

    cudaFuncSetAttribute(lstm_mma_kernel,
                         cudaFuncAttributeMaxDynamicSharedMemorySize, SMEM2_TOTAL);
    lstm_mma_kernel<<<NCTA, NT, SMEM2_TOTAL>>>(Whh,
                                               (const unsigned char*)mask,
                                               (const int*)mask,
                                               (const float*)mask,
                                               wci, wcf, wco, out);
}

// round 15
// speedup vs baseline: 1.3343x; 1.1043x over previous
#include <cuda_runtime.h>
#include <cuda_bf16.h>
#include <cuda_fp16.h>
#include <math.h>
#include <stdint.h>

#define BB 64
#define LL 1024
#define DD 512
#define HH 1024
#define GG 4096
#define NCTA 128
#define NT 256

// ---- phase-2 dynamic smem map: B slab (fp16) + 2 gate boards ----
#define SM_BHI 0                      // 32 x 1024 fp16 (swizzled)  64KB
#define SM_D   65536                  // 2 x (64 x 36) fp32 gate boards
#define SMEM2_TOTAL (SM_D + 2 * 64 * 36 * 4)   // 83968

// ---- phase-1 dynamic smem: 2 bufs x 64KB ----
#define SMEM1_TOTAL 131072

#define NX8 ((65536 * 512) / 8)
#define NW8 ((4096 * 512) / 8)

static __device__ float g_gx[(size_t)LL * BB * GG];   // [t][b][4H]
static __device__ __align__(16) __nv_bfloat16 g_xhi[(size_t)65536 * 512];
static __device__ __align__(16) __nv_bfloat16 g_xlo[(size_t)65536 * 512];
static __device__ __align__(16) __nv_bfloat16 g_whi[(size_t)4096 * 512];
static __device__ __align__(16) __nv_bfloat16 g_wlo[(size_t)4096 * 512];
// h published as pre-shuffled fp16 mma A-fragments:
// [buf][ktile 64][mtile 4][lane 32][reg 4] (uint32 = fp16x2)
static __device__ __align__(16) unsigned g_hfrag[2][64][4][32][4];
static __device__ unsigned g_bar[LL];
static __device__ int g_mask_mode;

__device__ __forceinline__ uint32_t smem_u32(const void* p) {
    uint32_t a;
    asm("{ .reg .u64 t; cvta.to.shared.u64 t, %1; cvt.u32.u64 %0, t; }" : "=r"(a) : "l"(p));
    return a;
}
__device__ __forceinline__ unsigned ldacq(const unsigned* p) {
    unsigned v;
    asm volatile("ld.acquire.gpu.global.u32 %0, [%1];" : "=r"(v) : "l"(p) : "memory");
    return v;
}
__device__ __forceinline__ void atomrel_add(unsigned* p, unsigned v) {
    unsigned old;
    asm volatile("atom.release.gpu.global.add.u32 %0, [%1], %2;"
                 : "=r"(old) : "l"(p), "r"(v) : "memory");
}
#define LDSM4(r, addr) asm volatile( \
    "ldmatrix.sync.aligned.m8n8.x4.shared.b16 {%0,%1,%2,%3}, [%4];" \
    : "=r"((r)[0]), "=r"((r)[1]), "=r"((r)[2]), "=r"((r)[3]) : "r"(addr))
#define LDSM2(r, addr) asm volatile( \
    "ldmatrix.sync.aligned.m8n8.x2.shared.b16 {%0,%1}, [%2];" \
    : "=r"((r)[0]), "=r"((r)[1]) : "r"(addr))
// bf16 mma (phase 1)
#define MMA16816(d, a, b) asm volatile( \
    "mma.sync.aligned.m16n8k16.row.col.f32.bf16.bf16.f32 " \
    "{%0,%1,%2,%3}, {%4,%5,%6,%7}, {%8,%9}, {%0,%1,%2,%3};" \
    : "+f"((d)[0]), "+f"((d)[1]), "+f"((d)[2]), "+f"((d)[3]) \
    : "r"((a)[0]), "r"((a)[1]), "r"((a)[2]), "r"((a)[3]), "r"((b)[0]), "r"((b)[1]))
// fp16 mma (phase 2)
#define MMAH16816(d, a, b) asm volatile( \
    "mma.sync.aligned.m16n8k16.row.col.f32.f16.f16.f32 " \
    "{%0,%1,%2,%3}, {%4,%5,%6,%7}, {%8,%9}, {%0,%1,%2,%3};" \
    : "+f"((d)[0]), "+f"((d)[1]), "+f"((d)[2]), "+f"((d)[3]) \
    : "r"((a)[0]), "r"((a)[1]), "r"((a)[2]), "r"((a)[3]), "r"((b)[0]), "r"((b)[1]))
#define CPA16(dst, src) asm volatile( \
    "cp.async.cg.shared.global [%0], [%1], 16;" :: "r"(dst), "l"(src))
#define CPCOMMIT() asm volatile("cp.async.commit_group;" ::: "memory")
#define CPWAIT0() asm volatile("cp.async.wait_group 0;" ::: "memory")

__device__ __forceinline__ float sigf(float x) { return 1.0f / (1.0f + __expf(-x)); }
__device__ __forceinline__ float tanhf_fast(float x) {
    float ax = fabsf(x);
    float e = __expf(2.0f * ax);
    float t = 1.0f - 2.0f / (e + 1.0f);
    return copysignf(t, x);
}

// ---------------- init --------------------------------------------------------
__global__ void init_kernel(const void* mask)
{
    int i = blockIdx.x * blockDim.x + threadIdx.x;
    // zero frag buffer 0 (h = 0): 64*4*32*4 = 32768 words
    if (i < 32768) ((unsigned*)g_hfrag)[i] = 0u;
    if (i < LL) g_bar[i] = 0u;
    if (i == 0) {
        int v = *(const int*)mask;          // lengths >= 512 -> mask[0,0..3] true
        if (v == 1)               g_mask_mode = 1;
        else if (v == 0x3F800000) g_mask_mode = 2;
        else                      g_mask_mode = 0;
    }
}

// ---------------- prep: fp32 -> bf16 hi/lo for X and Wih ---------------------
__global__ void convert_kernel(const float* __restrict__ X, const float* __restrict__ W)
{
    size_t s = (size_t)blockIdx.x * blockDim.x + threadIdx.x;
    const float* src;
    __nv_bfloat16 *dh, *dl;
    if (s < NX8)            { src = X + s * 8; dh = g_xhi + s * 8; dl = g_xlo + s * 8; }
    else if (s < NX8 + NW8) { size_t u = s - NX8; src = W + u * 8; dh = g_whi + u * 8; dl = g_wlo + u * 8; }
    else return;
    float4 f0 = *(const float4*)(src);
    float4 f1 = *(const float4*)(src + 4);
    float v[8] = {f0.x, f0.y, f0.z, f0.w, f1.x, f1.y, f1.z, f1.w};
    __align__(16) __nv_bfloat16 hi[8], lo[8];
#pragma unroll
    for (int j = 0; j < 8; j++) {
        __nv_bfloat16 h = __float2bfloat16(v[j]);
        hi[j] = h;
        lo[j] = __float2bfloat16(v[j] - __bfloat162float(h));
    }
    *(uint4*)dh = *(uint4*)hi;
    *(uint4*)dl = *(uint4*)lo;
}

// ---------------- phase 1: g_gx = X @ Wih^T + biases (bf16 hi/lo HMMA) -------
__global__ __launch_bounds__(256, 1)
void gemm_x_mma(const float* __restrict__ bih, const float* __restrict__ bhh)
{
    extern __shared__ __align__(16) char sm[];
    const uint32_t smb = smem_u32(sm);
    const int tid = threadIdx.x, lane = tid & 31, w = tid >> 5;
    const int wm = w & 1, wn = w >> 1;
    const int m0 = blockIdx.y * 128, n0 = blockIdx.x * 128;

    const int seg = lane >> 3, rr = lane & 7;
    const int adk = seg >> 1, bseg = seg & 1;

    const int lrow0 = tid >> 3, lc8 = tid & 7;
    const int soff0 = lrow0 * 128 + ((lc8 ^ (lrow0 & 7)) << 4);
    const __nv_bfloat16* xh = g_xhi + (size_t)(m0 + lrow0) * DD + lc8 * 8;
    const __nv_bfloat16* xl = g_xlo + (size_t)(m0 + lrow0) * DD + lc8 * 8;
    const __nv_bfloat16* wh = g_whi + (size_t)(n0 + lrow0) * DD + lc8 * 8;
    const __nv_bfloat16* wl = g_wlo + (size_t)(n0 + lrow0) * DD + lc8 * 8;

    int arow_off[4], brow_off[4];
#pragma unroll
    for (int mi = 0; mi < 4; mi++)
        arow_off[mi] = (wm * 64 + mi * 16 + ((seg & 1) << 3) + rr) * 128;
#pragma unroll
    for (int j = 0; j < 4; j++)
        brow_off[j] = (wn * 32 + j * 8 + rr) * 128;

    float bj0[4], bj1[4];
#pragma unroll
    for (int j = 0; j < 4; j++) {
        int col = n0 + wn * 32 + j * 8 + (lane & 3) * 2;
        bj0[j] = bih[col] + bhh[col];
        bj1[j] = bih[col + 1] + bhh[col + 1];
    }

    float acc[4][4][4];
#pragma unroll
    for (int mi = 0; mi < 4; mi++)
#pragma unroll
        for (int j = 0; j < 4; j++)
#pragma unroll
            for (int q = 0; q < 4; q++) acc[mi][j][q] = 0.0f;

    {
        uint32_t base = smb;
#pragma unroll
        for (int q = 0; q < 4; q++) {
            int go = q * 32 * DD;
            CPA16(base + soff0 + q * 4096,         xh + go);
            CPA16(base + 16384 + soff0 + q * 4096, xl + go);
            CPA16(base + 32768 + soff0 + q * 4096, wh + go);
            CPA16(base + 49152 + soff0 + q * 4096, wl + go);
        }
        CPCOMMIT();
    }

    for (int ck = 0; ck < 8; ++ck) {
        CPWAIT0();
        __syncthreads();
        if (ck < 7) {
            uint32_t base = smb + ((ck + 1) & 1) * 65536;
            int kofs = (ck + 1) * 64;
#pragma unroll
            for (int q = 0; q < 4; q++) {
                int go = q * 32 * DD + kofs;
                CPA16(base + soff0 + q * 4096,         xh + go);
                CPA16(base + 16384 + soff0 + q * 4096, xl + go);
                CPA16(base + 32768 + soff0 + q * 4096, wh + go);
                CPA16(base + 49152 + soff0 + q * 4096, wl + go);
            }
            CPCOMMIT();
        }
        const uint32_t bufA = smb + (ck & 1) * 65536;
        const uint32_t bufB = bufA + 32768;
#pragma unroll
        for (int ks = 0; ks < 4; ++ks) {
            uint32_t ah[4][4], al[4][4], bh[4][2], bl[4][2];
            const int ca = ((2 * ks + adk) ^ rr) << 4;
            const int cb = ((2 * ks + bseg) ^ rr) << 4;
#pragma unroll
            for (int mi = 0; mi < 4; mi++) {
                LDSM4(ah[mi], bufA + arow_off[mi] + ca);
                LDSM4(al[mi], bufA + 16384 + arow_off[mi] + ca);
            }
#pragma unroll
            for (int j = 0; j < 4; j++) {
                LDSM2(bh[j], bufB + brow_off[j] + cb);
                LDSM2(bl[j], bufB + 16384 + brow_off[j] + cb);
            }
#pragma unroll
            for (int mi = 0; mi < 4; mi++)
#pragma unroll
                for (int j = 0; j < 4; j++) {
                    MMA16816(acc[mi][j], ah[mi], bh[j]);
                    MMA16816(acc[mi][j], al[mi], bh[j]);
                    MMA16816(acc[mi][j], ah[mi], bl[j]);
                }
        }
        __syncthreads();
    }

#pragma unroll
    for (int mi = 0; mi < 4; mi++) {
        int r0 = m0 + wm * 64 + mi * 16 + (lane >> 2);
        int r1 = r0 + 8;
        float* d0 = g_gx + ((size_t)(r0 & 1023) * BB + (r0 >> 10)) * GG;
        float* d1 = g_gx + ((size_t)(r1 & 1023) * BB + (r1 >> 10)) * GG;
        int colb = n0 + wn * 32 + (lane & 3) * 2;
#pragma unroll
        for (int j = 0; j < 4; j++) {
            int col = colb + j * 8;
            *(float2*)(d0 + col) = make_float2(acc[mi][j][0] + bj0[j], acc[mi][j][1] + bj1[j]);
            *(float2*)(d1 + col) = make_float2(acc[mi][j][2] + bj0[j], acc[mi][j][3] + bj1[j]);
        }
    }
}

// ---------------- phase 2: persistent fp16 HMMA recurrence, k-split warps ----
// h and W both single fp16 (error budget measured: h-fp16 alone = 3.3e-5).
__global__ __launch_bounds__(NT, 1)
void lstm_mma_kernel(const float* __restrict__ Whh,
                     const unsigned char* __restrict__ m8,
                     const int* __restrict__ m32,
                     const float* __restrict__ mf,
                     const float* __restrict__ wci,
                     const float* __restrict__ wcf,
                     const float* __restrict__ wco,
                     float* __restrict__ out)
{
    extern __shared__ __align__(16) char sm[];
    const uint32_t smb = smem_u32(sm);

    const int tid  = threadIdx.x;
    const int lane = tid & 31;
    const int w    = tid >> 5;
    const int h0   = blockIdx.x * 8;

    // one-time: W slab -> smem fp16, 32 rows x 1024 k, swizzled (2048B rows)
    for (int s = tid; s < 4096; s += NT) {
        int n = s >> 7, c = s & 127;
        int gr = (n >> 3) * HH + h0 + (n & 7);
        const float* wp = Whh + (size_t)gr * HH + c * 8;
        __align__(16) __half hi8[8];
#pragma unroll
        for (int j = 0; j < 8; j++) hi8[j] = __float2half_rn(wp[j]);
        int off = n * 2048 + ((c ^ (n & 7)) << 4);
        *(uint4*)(sm + SM_BHI + off) = *(uint4*)hi8;
    }
    __syncthreads();

    // per-warp mma geometry: kh = k-half, mt = m-tile; all 4 n8-tiles
    const int kh  = w >> 2;
    const int mt  = w & 3;
    const int m0  = mt << 4;
    const int seg = lane >> 3, rr = lane & 7;
    const int brow_a = (((seg >> 1) << 3) + rr) * 2048;
    const int brow_b = ((16 + ((seg >> 1) << 3)) + rr) * 2048;
    const int bk_sel = seg & 1;
    float* Ds  = (float*)(sm + SM_D + kh * (64 * 36 * 4));
    float* Ds0 = (float*)(sm + SM_D);
    float* Ds1 = (float*)(sm + SM_D + 64 * 36 * 4);

    // epilogue geometry (tid < 128): row = tid>>1, col-half = tid&1
    const int erow  = tid >> 1;
    const int ehalf = tid & 1;
    // publisher geometry
    const int pkt   = blockIdx.x >> 1;
    const int pregb = (blockIdx.x & 1) * 2;

    // recurrent state (4 h-cols per thread)
    float c_reg[4], h_reg[4], rci[4], rcf[4], rco[4];
#pragma unroll
    for (int j = 0; j < 4; j++) { c_reg[j] = 0.0f; h_reg[j] = 0.0f; }
    if (tid < 128) {
#pragma unroll
        for (int j = 0; j < 4; j++) {
            int col = h0 + ehalf * 4 + j;
            rci[j] = wci[col]; rcf[j] = wcf[col]; rco[j] = wco[col];
        }
    }
    const int mmode = g_mask_mode;

// load B fragments for ktile `ktv` into register buffer `buf`
#define LOADB(buf, ktv) do {                                                  \
    const int _kg = ((kh * 32 + (ktv)) * 2 + bk_sel) ^ rr;                    \
    LDSM4(bh0[buf], smb + SM_BHI + brow_a + (_kg << 4));                      \
    LDSM4(bh1[buf], smb + SM_BHI + brow_b + (_kg << 4));                      \
} while (0)

    for (int t = 0; t < LL; ++t) {
        const int rbuf = t & 1;
        const unsigned* fph = &g_hfrag[rbuf][kh * 32][mt][lane][0];

        // prefetch x-projection + mask for the epilogue (128 threads)
        float gzi[4], gzf[4], gzg[4], gzo[4];
        bool mm = false;
        if (tid < 128) {
            const float* gx = g_gx + ((size_t)t * BB + erow) * GG + h0 + ehalf * 4;
            *(float4*)(&gzi[0]) = *(const float4*)(gx);
            *(float4*)(&gzf[0]) = *(const float4*)(gx + 1024);
            *(float4*)(&gzg[0]) = *(const float4*)(gx + 2048);
            *(float4*)(&gzo[0]) = *(const float4*)(gx + 3072);
            if (mmode == 1)      mm = (m32[erow * LL + t] != 0);
            else if (mmode == 2) mm = (mf[erow * LL + t] != 0.0f);
            else                 mm = (m8[erow * LL + t] != 0);
        }

        float d[4][4];
#pragma unroll
        for (int j = 0; j < 4; j++)
#pragma unroll
            for (int q = 0; q < 4; q++) d[j][q] = 0.0f;

        // A-fragment stream: 8-deep register prefetch; B double-buffered regs
        uint4 ph[8];
#pragma unroll
        for (int s = 0; s < 8; s++)
            ph[s] = __ldcg((const uint4*)(fph + (size_t)s * 512));
        uint32_t bh0[2][4], bh1[2][4];
        LOADB(0, 0);
#pragma unroll 8
        for (int kt = 0; kt < 32; ++kt) {
            const int cur = kt & 1, nxt = cur ^ 1;
            if (kt + 1 < 32) LOADB(nxt, kt + 1);
            uint32_t ah[4] = {ph[kt & 7].x, ph[kt & 7].y, ph[kt & 7].z, ph[kt & 7].w};
            if (kt + 8 < 32)
                ph[kt & 7] = __ldcg((const uint4*)(fph + (size_t)(kt + 8) * 512));
            MMAH16816(d[0], ah, (bh0[cur] + 0)); MMAH16816(d[1], ah, (bh0[cur] + 2));
            MMAH16816(d[2], ah, (bh1[cur] + 0)); MMAH16816(d[3], ah, (bh1[cur] + 2));
        }

        // accumulators -> this k-half's gate board
        {
            const int gid = lane >> 2, tig = lane & 3;
            const int dr0 = m0 + gid, dr1 = m0 + gid + 8;
#pragma unroll
            for (int j = 0; j < 4; j++) {
                int cc = j * 8 + 2 * tig;
                *(float2*)(&Ds[dr0 * 36 + cc]) = make_float2(d[j][0], d[j][1]);
                *(float2*)(&Ds[dr1 * 36 + cc]) = make_float2(d[j][2], d[j][3]);
            }
        }
        __syncthreads();

        // epilogue: 128 threads; thread owns 4 h-cols (all 4 gates) of one row
        if (tid < 128) {
            const int row = erow;
            const int cb  = ehalf * 4;
            float hv[4];
#pragma unroll
            for (int j = 0; j < 4; j++) {
                int cc = cb + j;
                float vi = gzi[j] + Ds0[row * 36 + cc]      + Ds1[row * 36 + cc];
                float vf = gzf[j] + Ds0[row * 36 + 8 + cc]  + Ds1[row * 36 + 8 + cc];
                float vg = gzg[j] + Ds0[row * 36 + 16 + cc] + Ds1[row * 36 + 16 + cc];
                float vo = gzo[j] + Ds0[row * 36 + 24 + cc] + Ds1[row * 36 + 24 + cc];
                float cold = c_reg[j];
                float iv = sigf(vi + rci[j] * cold);
                float fv = sigf(vf + rcf[j] * cold);
                float gv = tanhf_fast(vg);
                float cy = fv * cold + iv * gv;
                float ov = sigf(vo + rco[j] * cy);
                float hy = ov * tanhf_fast(cy);
                if (mm) { c_reg[j] = cy; h_reg[j] = hy; }
                hv[j] = h_reg[j];
            }
            float* op = out + ((size_t)row * LL + t) * HH + h0 + cb;
            *(float4*)(op) = make_float4(hv[0], hv[1], hv[2], hv[3]);

            // publish h as pre-shuffled fp16 mma A-fragments: 2 packed pairs
            const int wbuf  = (t + 1) & 1;
            const int pmt   = row >> 4;
            const int lbase = 4 * (row & 7);
            const int preg  = pregb + ((row & 15) >> 3);
            unsigned* dsth = &g_hfrag[wbuf][pkt][pmt][0][0];
#pragma unroll
            for (int p2 = 0; p2 < 2; p2++) {
                const int p = ehalf * 2 + p2;
                __half h0h = __float2half_rn(hv[2 * p2]);
                __half h1h = __float2half_rn(hv[2 * p2 + 1]);
                unsigned uh = (unsigned)__half_as_ushort(h0h) |
                              ((unsigned)__half_as_ushort(h1h) << 16);
                dsth[(lbase + p) * 4 + preg] = uh;
            }

            if (t == LL - 1) {
                float* hf = out + (size_t)BB * LL * HH + row * HH + h0 + cb;
                float* cf = hf + (size_t)BB * HH;
                *(float4*)(hf) = make_float4(hv[0], hv[1], hv[2], hv[3]);
                *(float4*)(cf) = make_float4(c_reg[0], c_reg[1], c_reg[2], c_reg[3]);
            }
        }

        // grid-wide barrier: bar.sync gives HB from all epilogue stores to tid 0;
        // release-atomic publishes them GPU-wide; waiters acquire-poll.
        __syncthreads();
        if (tid == 0) {
            atomrel_add(&g_bar[t], 1u);
            while (ldacq(&g_bar[t]) < (unsigned)gridDim.x) __nanosleep(64);
        }
        __syncthreads();
    }
#undef LOADB
}

// ---------------- launch ------------------------------------------------------
extern "C" void kernel_launch(void* const* d_in, const int* in_sizes, int n_in,
                              void* d_out, int out_size)
{
    (void)in_sizes; (void)n_in; (void)out_size;
    const float* X    = (const float*)d_in[0];
    const void*  mask = d_in[1];
    const float* Wih  = (const float*)d_in[2];
    const float* Whh  = (const float*)d_in[3];
    const float* bih  = (const float*)d_in[4];
    const float* bhh  = (const float*)d_in[5];
    const float* wci  = (const float*)d_in[6];
    const float* wcf  = (const float*)d_in[7];
    const float* wco  = (const float*)d_in[8];
    float* out = (float*)d_out;

    init_kernel<<<256, 256>>>(mask);
    convert_kernel<<<(NX8 + NW8 + 255) / 256, 256>>>(X, Wih);

    cudaFuncSetAttribute(gemm_x_mma,
                         cudaFuncAttributeMaxDynamicSharedMemorySize, SMEM1_TOTAL);
    dim3 g1(GG / 128, (BB * LL) / 128);
    gemm_x_mma<<<g1, 256, SMEM1_TOTAL>>>(bih, bhh);

    cudaFuncSetAttribute(lstm_mma_kernel,
                         cudaFuncAttributeMaxDynamicSharedMemorySize, SMEM2_TOTAL);
    lstm_mma_kernel<<<NCTA, NT, SMEM2_TOTAL>>>(Whh,
                                               (const unsigned char*)mask,
                                               (const int*)mask,
                                               (const float*)mask,
                                               wci, wcf, wco, out);
}

// round 16
// speedup vs baseline: 1.5406x; 1.1547x over previous
#include <cuda_runtime.h>
#include <cuda_bf16.h>
#include <cuda_fp16.h>
#include <math.h>
#include <stdint.h>

#define BB 64
#define LL 1024
#define DD 512
#define HH 1024
#define GG 4096
#define NCTA 128
#define NT 256

// ---- phase-2 dynamic smem map: B slab (fp16) + 2 gate boards ----
#define SM_BHI 0                      // 32 x 1024 fp16 (swizzled)  64KB
#define SM_D   65536                  // 2 x (64 x 36) fp32 gate boards
#define SMEM2_TOTAL (SM_D + 2 * 64 * 36 * 4)   // 83968

// ---- phase-1 dynamic smem: 2 bufs x 32KB (A 16KB + B 16KB) ----
#define SMEM1_TOTAL 65536

#define NX8 ((65536 * 512) / 8)
#define NW8 ((4096 * 512) / 8)

static __device__ float g_gx[(size_t)LL * BB * GG];   // [t][b][4H]
static __device__ __align__(16) __half g_xh[(size_t)65536 * 512];
static __device__ __align__(16) __half g_wh[(size_t)4096 * 512];
// h published as pre-shuffled fp16 mma A-fragments:
// [buf][ktile 64][mtile 4][lane 32][reg 4] (uint32 = fp16x2)
static __device__ __align__(16) unsigned g_hfrag[2][64][4][32][4];
static __device__ unsigned g_bar[LL];
static __device__ int g_mask_mode;

__device__ __forceinline__ uint32_t smem_u32(const void* p) {
    uint32_t a;
    asm("{ .reg .u64 t; cvta.to.shared.u64 t, %1; cvt.u32.u64 %0, t; }" : "=r"(a) : "l"(p));
    return a;
}
__device__ __forceinline__ unsigned ldacq(const unsigned* p) {
    unsigned v;
    asm volatile("ld.acquire.gpu.global.u32 %0, [%1];" : "=r"(v) : "l"(p) : "memory");
    return v;
}
__device__ __forceinline__ void atomrel_add(unsigned* p, unsigned v) {
    unsigned old;
    asm volatile("atom.release.gpu.global.add.u32 %0, [%1], %2;"
                 : "=r"(old) : "l"(p), "r"(v) : "memory");
}
#define LDSM4(r, addr) asm volatile( \
    "ldmatrix.sync.aligned.m8n8.x4.shared.b16 {%0,%1,%2,%3}, [%4];" \
    : "=r"((r)[0]), "=r"((r)[1]), "=r"((r)[2]), "=r"((r)[3]) : "r"(addr))
#define LDSM2(r, addr) asm volatile( \
    "ldmatrix.sync.aligned.m8n8.x2.shared.b16 {%0,%1}, [%2];" \
    : "=r"((r)[0]), "=r"((r)[1]) : "r"(addr))
// fp16 mma
#define MMAH16816(d, a, b) asm volatile( \
    "mma.sync.aligned.m16n8k16.row.col.f32.f16.f16.f32 " \
    "{%0,%1,%2,%3}, {%4,%5,%6,%7}, {%8,%9}, {%0,%1,%2,%3};" \
    : "+f"((d)[0]), "+f"((d)[1]), "+f"((d)[2]), "+f"((d)[3]) \
    : "r"((a)[0]), "r"((a)[1]), "r"((a)[2]), "r"((a)[3]), "r"((b)[0]), "r"((b)[1]))
#define CPA16(dst, src) asm volatile( \
    "cp.async.cg.shared.global [%0], [%1], 16;" :: "r"(dst), "l"(src))
#define CPCOMMIT() asm volatile("cp.async.commit_group;" ::: "memory")
#define CPWAIT0() asm volatile("cp.async.wait_group 0;" ::: "memory")

__device__ __forceinline__ float sigf(float x) { return 1.0f / (1.0f + __expf(-x)); }
__device__ __forceinline__ float tanhf_fast(float x) {
    float ax = fabsf(x);
    float e = __expf(2.0f * ax);
    float t = 1.0f - 2.0f / (e + 1.0f);
    return copysignf(t, x);
}

// ---------------- init --------------------------------------------------------
__global__ void init_kernel(const void* mask)
{
    int i = blockIdx.x * blockDim.x + threadIdx.x;
    // zero frag buffer 0 (h = 0): 64*4*32*4 = 32768 words
    if (i < 32768) ((unsigned*)g_hfrag)[i] = 0u;
    if (i < LL) g_bar[i] = 0u;
    if (i == 0) {
        int v = *(const int*)mask;          // lengths >= 512 -> mask[0,0..3] true
        if (v == 1)               g_mask_mode = 1;
        else if (v == 0x3F800000) g_mask_mode = 2;
        else                      g_mask_mode = 0;
    }
}

// ---------------- prep: fp32 -> fp16 for X and Wih ----------------------------
__global__ void convert_kernel(const float* __restrict__ X, const float* __restrict__ W)
{
    size_t s = (size_t)blockIdx.x * blockDim.x + threadIdx.x;
    const float* src;
    __half* dh;
    if (s < NX8)            { src = X + s * 8; dh = g_xh + s * 8; }
    else if (s < NX8 + NW8) { size_t u = s - NX8; src = W + u * 8; dh = g_wh + u * 8; }
    else return;
    float4 f0 = *(const float4*)(src);
    float4 f1 = *(const float4*)(src + 4);
    float v[8] = {f0.x, f0.y, f0.z, f0.w, f1.x, f1.y, f1.z, f1.w};
    __align__(16) __half hi[8];
#pragma unroll
    for (int j = 0; j < 8; j++) hi[j] = __float2half_rn(v[j]);
    *(uint4*)dh = *(uint4*)hi;
}

// ---------------- phase 1: g_gx = X @ Wih^T + biases (fp16 HMMA, 1 pass) -----
__global__ __launch_bounds__(256, 1)
void gemm_x_mma(const float* __restrict__ bih, const float* __restrict__ bhh)
{
    extern __shared__ __align__(16) char sm[];
    const uint32_t smb = smem_u32(sm);
    const int tid = threadIdx.x, lane = tid & 31, w = tid >> 5;
    const int wm = w & 1, wn = w >> 1;
    const int m0 = blockIdx.y * 128, n0 = blockIdx.x * 128;

    const int seg = lane >> 3, rr = lane & 7;
    const int adk = seg >> 1, bseg = seg & 1;

    const int lrow0 = tid >> 3, lc8 = tid & 7;
    const int soff0 = lrow0 * 128 + ((lc8 ^ (lrow0 & 7)) << 4);
    const __half* xh = g_xh + (size_t)(m0 + lrow0) * DD + lc8 * 8;
    const __half* wh = g_wh + (size_t)(n0 + lrow0) * DD + lc8 * 8;

    int arow_off[4], brow_off[4];
#pragma unroll
    for (int mi = 0; mi < 4; mi++)
        arow_off[mi] = (wm * 64 + mi * 16 + ((seg & 1) << 3) + rr) * 128;
#pragma unroll
    for (int j = 0; j < 4; j++)
        brow_off[j] = (wn * 32 + j * 8 + rr) * 128;

    float bj0[4], bj1[4];
#pragma unroll
    for (int j = 0; j < 4; j++) {
        int col = n0 + wn * 32 + j * 8 + (lane & 3) * 2;
        bj0[j] = bih[col] + bhh[col];
        bj1[j] = bih[col + 1] + bhh[col + 1];
    }

    float acc[4][4][4];
#pragma unroll
    for (int mi = 0; mi < 4; mi++)
#pragma unroll
        for (int j = 0; j < 4; j++)
#pragma unroll
            for (int q = 0; q < 4; q++) acc[mi][j][q] = 0.0f;

    {
        uint32_t base = smb;
#pragma unroll
        for (int q = 0; q < 4; q++) {
            int go = q * 32 * DD;
            CPA16(base + soff0 + q * 4096,         xh + go);
            CPA16(base + 16384 + soff0 + q * 4096, wh + go);
        }
        CPCOMMIT();
    }

    for (int ck = 0; ck < 8; ++ck) {
        CPWAIT0();
        __syncthreads();
        if (ck < 7) {
            uint32_t base = smb + ((ck + 1) & 1) * 32768;
            int kofs = (ck + 1) * 64;
#pragma unroll
            for (int q = 0; q < 4; q++) {
                int go = q * 32 * DD + kofs;
                CPA16(base + soff0 + q * 4096,         xh + go);
                CPA16(base + 16384 + soff0 + q * 4096, wh + go);
            }
            CPCOMMIT();
        }
        const uint32_t bufA = smb + (ck & 1) * 32768;
        const uint32_t bufB = bufA + 16384;
#pragma unroll
        for (int ks = 0; ks < 4; ++ks) {
            uint32_t ah[4][4], bh[4][2];
            const int ca = ((2 * ks + adk) ^ rr) << 4;
            const int cb = ((2 * ks + bseg) ^ rr) << 4;
#pragma unroll
            for (int mi = 0; mi < 4; mi++)
                LDSM4(ah[mi], bufA + arow_off[mi] + ca);
#pragma unroll
            for (int j = 0; j < 4; j++)
                LDSM2(bh[j], bufB + brow_off[j] + cb);
#pragma unroll
            for (int mi = 0; mi < 4; mi++)
#pragma unroll
                for (int j = 0; j < 4; j++)
                    MMAH16816(acc[mi][j], ah[mi], bh[j]);
        }
        __syncthreads();
    }

#pragma unroll
    for (int mi = 0; mi < 4; mi++) {
        int r0 = m0 + wm * 64 + mi * 16 + (lane >> 2);
        int r1 = r0 + 8;
        float* d0 = g_gx + ((size_t)(r0 & 1023) * BB + (r0 >> 10)) * GG;
        float* d1 = g_gx + ((size_t)(r1 & 1023) * BB + (r1 >> 10)) * GG;
        int colb = n0 + wn * 32 + (lane & 3) * 2;
#pragma unroll
        for (int j = 0; j < 4; j++) {
            int col = colb + j * 8;
            *(float2*)(d0 + col) = make_float2(acc[mi][j][0] + bj0[j], acc[mi][j][1] + bj1[j]);
            *(float2*)(d1 + col) = make_float2(acc[mi][j][2] + bj0[j], acc[mi][j][3] + bj1[j]);
        }
    }
}

// ---------------- phase 2: persistent fp16 HMMA recurrence, k-split warps ----
// (unchanged from R15 winner)
__global__ __launch_bounds__(NT, 1)
void lstm_mma_kernel(const float* __restrict__ Whh,
                     const unsigned char* __restrict__ m8,
                     const int* __restrict__ m32,
                     const float* __restrict__ mf,
                     const float* __restrict__ wci,
                     const float* __restrict__ wcf,
                     const float* __restrict__ wco,
                     float* __restrict__ out)
{
    extern __shared__ __align__(16) char sm[];
    const uint32_t smb = smem_u32(sm);

    const int tid  = threadIdx.x;
    const int lane = tid & 31;
    const int w    = tid >> 5;
    const int h0   = blockIdx.x * 8;

    // one-time: W slab -> smem fp16, 32 rows x 1024 k, swizzled (2048B rows)
    for (int s = tid; s < 4096; s += NT) {
        int n = s >> 7, c = s & 127;
        int gr = (n >> 3) * HH + h0 + (n & 7);
        const float* wp = Whh + (size_t)gr * HH + c * 8;
        __align__(16) __half hi8[8];
#pragma unroll
        for (int j = 0; j < 8; j++) hi8[j] = __float2half_rn(wp[j]);
        int off = n * 2048 + ((c ^ (n & 7)) << 4);
        *(uint4*)(sm + SM_BHI + off) = *(uint4*)hi8;
    }
    __syncthreads();

    // per-warp mma geometry: kh = k-half, mt = m-tile; all 4 n8-tiles
    const int kh  = w >> 2;
    const int mt  = w & 3;
    const int m0  = mt << 4;
    const int seg = lane >> 3, rr = lane & 7;
    const int brow_a = (((seg >> 1) << 3) + rr) * 2048;
    const int brow_b = ((16 + ((seg >> 1) << 3)) + rr) * 2048;
    const int bk_sel = seg & 1;
    float* Ds  = (float*)(sm + SM_D + kh * (64 * 36 * 4));
    float* Ds0 = (float*)(sm + SM_D);
    float* Ds1 = (float*)(sm + SM_D + 64 * 36 * 4);

    // epilogue geometry (tid < 128): row = tid>>1, col-half = tid&1
    const int erow  = tid >> 1;
    const int ehalf = tid & 1;
    // publisher geometry
    const int pkt   = blockIdx.x >> 1;
    const int pregb = (blockIdx.x & 1) * 2;

    // recurrent state (4 h-cols per thread)
    float c_reg[4], h_reg[4], rci[4], rcf[4], rco[4];
#pragma unroll
    for (int j = 0; j < 4; j++) { c_reg[j] = 0.0f; h_reg[j] = 0.0f; }
    if (tid < 128) {
#pragma unroll
        for (int j = 0; j < 4; j++) {
            int col = h0 + ehalf * 4 + j;
            rci[j] = wci[col]; rcf[j] = wcf[col]; rco[j] = wco[col];
        }
    }
    const int mmode = g_mask_mode;

// load B fragments for ktile `ktv` into register buffer `buf`
#define LOADB(buf, ktv) do {                                                  \
    const int _kg = ((kh * 32 + (ktv)) * 2 + bk_sel) ^ rr;                    \
    LDSM4(bh0[buf], smb + SM_BHI + brow_a + (_kg << 4));                      \
    LDSM4(bh1[buf], smb + SM_BHI + brow_b + (_kg << 4));                      \
} while (0)

    for (int t = 0; t < LL; ++t) {
        const int rbuf = t & 1;
        const unsigned* fph = &g_hfrag[rbuf][kh * 32][mt][lane][0];

        // prefetch x-projection + mask for the epilogue (128 threads)
        float gzi[4], gzf[4], gzg[4], gzo[4];
        bool mm = false;
        if (tid < 128) {
            const float* gx = g_gx + ((size_t)t * BB + erow) * GG + h0 + ehalf * 4;
            *(float4*)(&gzi[0]) = *(const float4*)(gx);
            *(float4*)(&gzf[0]) = *(const float4*)(gx + 1024);
            *(float4*)(&gzg[0]) = *(const float4*)(gx + 2048);
            *(float4*)(&gzo[0]) = *(const float4*)(gx + 3072);
            if (mmode == 1)      mm = (m32[erow * LL + t] != 0);
            else if (mmode == 2) mm = (mf[erow * LL + t] != 0.0f);
            else                 mm = (m8[erow * LL + t] != 0);
        }

        float d[4][4];
#pragma unroll
        for (int j = 0; j < 4; j++)
#pragma unroll
            for (int q = 0; q < 4; q++) d[j][q] = 0.0f;

        // A-fragment stream: 8-deep register prefetch; B double-buffered regs
        uint4 ph[8];
#pragma unroll
        for (int s = 0; s < 8; s++)
            ph[s] = __ldcg((const uint4*)(fph + (size_t)s * 512));
        uint32_t bh0[2][4], bh1[2][4];
        LOADB(0, 0);
#pragma unroll 8
        for (int kt = 0; kt < 32; ++kt) {
            const int cur = kt & 1, nxt = cur ^ 1;
            if (kt + 1 < 32) LOADB(nxt, kt + 1);
            uint32_t ah[4] = {ph[kt & 7].x, ph[kt & 7].y, ph[kt & 7].z, ph[kt & 7].w};
            if (kt + 8 < 32)
                ph[kt & 7] = __ldcg((const uint4*)(fph + (size_t)(kt + 8) * 512));
            MMAH16816(d[0], ah, (bh0[cur] + 0)); MMAH16816(d[1], ah, (bh0[cur] + 2));
            MMAH16816(d[2], ah, (bh1[cur] + 0)); MMAH16816(d[3], ah, (bh1[cur] + 2));
        }

        // accumulators -> this k-half's gate board
        {
            const int gid = lane >> 2, tig = lane & 3;
            const int dr0 = m0 + gid, dr1 = m0 + gid + 8;
#pragma unroll
            for (int j = 0; j < 4; j++) {
                int cc = j * 8 + 2 * tig;
                *(float2*)(&Ds[dr0 * 36 + cc]) = make_float2(d[j][0], d[j][1]);
                *(float2*)(&Ds[dr1 * 36 + cc]) = make_float2(d[j][2], d[j][3]);
            }
        }
        __syncthreads();

        // epilogue: 128 threads; thread owns 4 h-cols (all 4 gates) of one row
        if (tid < 128) {
            const int row = erow;
            const int cb  = ehalf * 4;
            float hv[4];
#pragma unroll
            for (int j = 0; j < 4; j++) {
                int cc = cb + j;
                float vi = gzi[j] + Ds0[row * 36 + cc]      + Ds1[row * 36 + cc];
                float vf = gzf[j] + Ds0[row * 36 + 8 + cc]  + Ds1[row * 36 + 8 + cc];
                float vg = gzg[j] + Ds0[row * 36 + 16 + cc] + Ds1[row * 36 + 16 + cc];
                float vo = gzo[j] + Ds0[row * 36 + 24 + cc] + Ds1[row * 36 + 24 + cc];
                float cold = c_reg[j];
                float iv = sigf(vi + rci[j] * cold);
                float fv = sigf(vf + rcf[j] * cold);
                float gv = tanhf_fast(vg);
                float cy = fv * cold + iv * gv;
                float ov = sigf(vo + rco[j] * cy);
                float hy = ov * tanhf_fast(cy);
                if (mm) { c_reg[j] = cy; h_reg[j] = hy; }
                hv[j] = h_reg[j];
            }
            float* op = out + ((size_t)row * LL + t) * HH + h0 + cb;
            *(float4*)(op) = make_float4(hv[0], hv[1], hv[2], hv[3]);

            // publish h as pre-shuffled fp16 mma A-fragments: 2 packed pairs
            const int wbuf  = (t + 1) & 1;
            const int pmt   = row >> 4;
            const int lbase = 4 * (row & 7);
            const int preg  = pregb + ((row & 15) >> 3);
            unsigned* dsth = &g_hfrag[wbuf][pkt][pmt][0][0];
#pragma unroll
            for (int p2 = 0; p2 < 2; p2++) {
                const int p = ehalf * 2 + p2;
                __half h0h = __float2half_rn(hv[2 * p2]);
                __half h1h = __float2half_rn(hv[2 * p2 + 1]);
                unsigned uh = (unsigned)__half_as_ushort(h0h) |
                              ((unsigned)__half_as_ushort(h1h) << 16);
                dsth[(lbase + p) * 4 + preg] = uh;
            }

            if (t == LL - 1) {
                float* hf = out + (size_t)BB * LL * HH + row * HH + h0 + cb;
                float* cf = hf + (size_t)BB * HH;
                *(float4*)(hf) = make_float4(hv[0], hv[1], hv[2], hv[3]);
                *(float4*)(cf) = make_float4(c_reg[0], c_reg[1], c_reg[2], c_reg[3]);
            }
        }

        // grid-wide barrier: bar.sync gives HB from all epilogue stores to tid 0;
        // release-atomic publishes them GPU-wide; waiters acquire-poll.
        __syncthreads();
        if (tid == 0) {
            atomrel_add(&g_bar[t], 1u);
            while (ldacq(&g_bar[t]) < (unsigned)gridDim.x) __nanosleep(64);
        }
        __syncthreads();
    }
#undef LOADB
}

// ---------------- launch ------------------------------------------------------
extern "C" void kernel_launch(void* const* d_in, const int* in_sizes, int n_in,
                              void* d_out, int out_size)
{
    (void)in_sizes; (void)n_in; (void)out_size;
    const float* X    = (const float*)d_in[0];
    const void*  mask = d_in[1];
    const float* Wih  = (const float*)d_in[2];
    const float* Whh  = (const float*)d_in[3];
    const float* bih  = (const float*)d_in[4];
    const float* bhh  = (const float*)d_in[5];
    const float* wci  = (const float*)d_in[6];
    const float* wcf  = (const float*)d_in[7];
    const float* wco  = (const float*)d_in[8];
    float* out = (float*)d_out;

    init_kernel<<<256, 256>>>(mask);
    convert_kernel<<<(NX8 + NW8 + 255) / 256, 256>>>(X, Wih);

    cudaFuncSetAttribute(gemm_x_mma,
                         cudaFuncAttributeMaxDynamicSharedMemorySize, SMEM1_TOTAL);
    dim3 g1(GG / 128, (BB * LL) / 128);
    gemm_x_mma<<<g1, 256, SMEM1_TOTAL>>>(bih, bhh);

    cudaFuncSetAttribute(lstm_mma_kernel,
                         cudaFuncAttributeMaxDynamicSharedMemorySize, SMEM2_TOTAL);
    lstm_mma_kernel<<<NCTA, NT, SMEM2_TOTAL>>>(Whh,
                                               (const unsigned char*)mask,
                                               (const int*)mask,
                                               (const float*)mask,
                                               wci, wcf, wco, out);
}